// round 6
// baseline (speedup 1.0000x reference)
#include <cuda_runtime.h>
#include <cuda_bf16.h>
#include <cstdint>

#define D 64
#define KNB 64
#define PAD 68     // f32 smem row stride (words)
#define PADB 72    // bf16 smem row stride (elements)

// ---------------- prepped weights in global ----------------
__device__ float g_W1[D * D];                         // [d][f]   rows for hs matvec
__device__ float g_W2t[D * D];                        // [f][d]   rows for g matvec
__device__ __align__(16) unsigned short g_Bhi[D * PADB];  // W2 bf16 hi, [d][f] padded
__device__ __align__(16) unsigned short g_Blo[D * PADB];  // W2 bf16 lo residual

__device__ __forceinline__ uint32_t smem_u32(const void* p) {
    uint32_t a;
    asm("{ .reg .u64 t; cvta.to.shared.u64 t, %1; cvt.u32.u64 %0, t; }" : "=r"(a) : "l"(p));
    return a;
}
__device__ __forceinline__ void cp16(uint32_t s, const void* g) {
    asm volatile("cp.async.cg.shared.global [%0], [%1], 16;" :: "r"(s), "l"(g));
}
#define CP_COMMIT_WAIT() do { \
    asm volatile("cp.async.commit_group;" ::: "memory"); \
    asm volatile("cp.async.wait_group 0;" ::: "memory"); } while (0)

#define MMA(ac, A, B0, B1) \
    asm volatile("mma.sync.aligned.m16n8k16.row.col.f32.bf16.bf16.f32 " \
        "{%0,%1,%2,%3}, {%4,%5,%6,%7}, {%8,%9}, {%0,%1,%2,%3};" \
        : "+f"((ac)[0]), "+f"((ac)[1]), "+f"((ac)[2]), "+f"((ac)[3]) \
        : "r"((A)[0]), "r"((A)[1]), "r"((A)[2]), "r"((A)[3]), "r"(B0), "r"(B1))

__device__ __forceinline__ void split2(float2 f, unsigned& hi, unsigned& lo) {
    unsigned u0 = __float_as_uint(f.x), u1 = __float_as_uint(f.y);
    hi = (u0 >> 16) | (u1 & 0xFFFF0000u);
    float l0 = f.x - __uint_as_float(u0 & 0xFFFF0000u);
    float l1 = f.y - __uint_as_float(u1 & 0xFFFF0000u);
    __nv_bfloat162 p = __floats2bfloat162_rn(l0, l1);
    lo = *reinterpret_cast<unsigned*>(&p);
}
__device__ __forceinline__ float dot4(const float4& a, const float4& b) {
    return a.x * b.x + a.y * b.y + a.z * b.z + a.w * b.w;
}

// ---------------- prep kernel ----------------
__global__ void prep_kernel(const float* __restrict__ fc_w) {
    int i = blockIdx.x * 256 + threadIdx.x;
    if (i < D * 2 * D) {
        int d = i >> 7, f = i & 127;
        float v = fc_w[i];
        if (f < 64) {
            g_W1[d * 64 + f] = v;
        } else {
            int f2 = f - 64;
            g_W2t[f2 * 64 + d] = v;
            unsigned u = __float_as_uint(v);
            g_Bhi[d * PADB + f2] = (unsigned short)(u >> 16);
            float lo = v - __uint_as_float(u & 0xFFFF0000u);
            g_Blo[d * PADB + f2] = __bfloat16_as_ushort(__float2bfloat16(lo));
        }
    }
}

// ---------------- main fused kernel ----------------
__global__ void __launch_bounds__(256, 3) kgat_kernel(
    const float* __restrict__ src_embs,
    const float* __restrict__ dst_embs,
    const float* __restrict__ rel_embs,
    const float* __restrict__ fc_b,
    const int*   __restrict__ mask,
    float* __restrict__ out)
{
    extern __shared__ __align__(16) float smem[];
    float* sdst = smem;                              // [64][PAD] f32
    float* srel = sdst + KNB * PAD;                  // [64][PAD] f32
    unsigned short* sBhi = (unsigned short*)(srel + KNB * PAD);  // [64][PADB]
    unsigned short* sBlo = sBhi + D * PADB;

    __shared__ __align__(16) float ssrc[D], shs[D], sg[D], sb[D];
    __shared__ float sc1[KNB], sc2[KNB], sr2[KNB];
    __shared__ float sdr[KNB], sdh[KNB], satt[KNB];
    __shared__ float sred1[128], sred2[128], sagg[256];
    __shared__ int   smask[KNB];
    __shared__ float s_s2;

    const int n = blockIdx.x;
    const int t = threadIdx.x;
    const int w = t >> 5, l = t & 31;
    const int g = l >> 2, tg = l & 3;

    const float4* gdst4 = (const float4*)(dst_embs + (size_t)n * (KNB * D));
    const float4* grel4 = (const float4*)(rel_embs + (size_t)n * (KNB * D));

    // ---- prologue: cp.async everything big ----
    for (int i = t; i < KNB * D / 4; i += 256) {
        int k = i >> 4, c4 = i & 15;
        cp16(smem_u32(&sdst[k * PAD + c4 * 4]), gdst4 + i);
        cp16(smem_u32(&srel[k * PAD + c4 * 4]), grel4 + i);
    }
    for (int i = t; i < D * PADB * 2 / 16; i += 256) {   // 576 chunks
        cp16(smem_u32(sBhi) + i * 16, ((const float4*)g_Bhi) + i);
        cp16(smem_u32(sBlo) + i * 16, ((const float4*)g_Blo) + i);
    }
    if (t < D) {
        ssrc[t] = src_embs[(size_t)n * D + t];
        sb[t] = fc_b[t];
        smask[t] = mask[(size_t)n * KNB + t];
    }
    CP_COMMIT_WAIT();
    __syncthreads();

    // ===================== HMMA GEMM: hd = dst @ W2^T (bf16 hi/lo) =====================
    // warp pair (w>>1) owns m-tile (16 k-rows); w&1 picks n-half (32 d-cols).
    {
        const int m0 = (w >> 1) * 16;
        const int nh = w & 1;
        float acc[4][4];
#pragma unroll
        for (int i = 0; i < 4; i++)
#pragma unroll
            for (int j = 0; j < 4; j++) acc[i][j] = 0.f;

#pragma unroll
        for (int ks = 0; ks < 4; ks++) {
            const int k0 = ks * 16;
            // A fragments from f32 sdst, on-the-fly bf16 hi/lo split
            float2 fA0 = *(const float2*)&sdst[(m0 + g) * PAD + k0 + 2 * tg];
            float2 fA1 = *(const float2*)&sdst[(m0 + g + 8) * PAD + k0 + 2 * tg];
            float2 fA2 = *(const float2*)&sdst[(m0 + g) * PAD + k0 + 2 * tg + 8];
            float2 fA3 = *(const float2*)&sdst[(m0 + g + 8) * PAD + k0 + 2 * tg + 8];
            unsigned Ahi[4], Alo[4];
            split2(fA0, Ahi[0], Alo[0]);
            split2(fA1, Ahi[1], Alo[1]);
            split2(fA2, Ahi[2], Alo[2]);
            split2(fA3, Ahi[3], Alo[3]);
#pragma unroll
            for (int nt = 0; nt < 4; nt++) {
                const int n0 = nh * 32 + nt * 8;
                const unsigned short* bh = &sBhi[(n0 + g) * PADB + k0 + 2 * tg];
                const unsigned short* bl = &sBlo[(n0 + g) * PADB + k0 + 2 * tg];
                unsigned Bh0 = *(const unsigned*)bh;
                unsigned Bh1 = *(const unsigned*)(bh + 8);
                unsigned Bl0 = *(const unsigned*)bl;
                unsigned Bl1 = *(const unsigned*)(bl + 8);
                MMA(acc[nt], Ahi, Bh0, Bh1);
                MMA(acc[nt], Alo, Bh0, Bh1);
                MMA(acc[nt], Ahi, Bl0, Bl1);
            }
        }
        // epilogue: c1 = <hd,rel>, c2 = ||hd||^2 per k-row, from D fragments
        float c1p0 = 0.f, c1p1 = 0.f, c2p0 = 0.f, c2p1 = 0.f;
#pragma unroll
        for (int nt = 0; nt < 4; nt++) {
            const int c = nh * 32 + nt * 8 + 2 * tg;
            float2 re0 = *(const float2*)&srel[(m0 + g) * PAD + c];
            float2 re1 = *(const float2*)&srel[(m0 + g + 8) * PAD + c];
            c1p0 += acc[nt][0] * re0.x + acc[nt][1] * re0.y;
            c1p1 += acc[nt][2] * re1.x + acc[nt][3] * re1.y;
            c2p0 += acc[nt][0] * acc[nt][0] + acc[nt][1] * acc[nt][1];
            c2p1 += acc[nt][2] * acc[nt][2] + acc[nt][3] * acc[nt][3];
        }
        c1p0 += __shfl_xor_sync(0xffffffffu, c1p0, 1);
        c1p1 += __shfl_xor_sync(0xffffffffu, c1p1, 1);
        c2p0 += __shfl_xor_sync(0xffffffffu, c2p0, 1);
        c2p1 += __shfl_xor_sync(0xffffffffu, c2p1, 1);
        c1p0 += __shfl_xor_sync(0xffffffffu, c1p0, 2);
        c1p1 += __shfl_xor_sync(0xffffffffu, c1p1, 2);
        c2p0 += __shfl_xor_sync(0xffffffffu, c2p0, 2);
        c2p1 += __shfl_xor_sync(0xffffffffu, c2p1, 2);
        if (tg == 0) {
            sred1[nh * 64 + m0 + g] = c1p0;
            sred1[nh * 64 + m0 + g + 8] = c1p1;
            sred2[nh * 64 + m0 + g] = c2p0;
            sred2[nh * 64 + m0 + g + 8] = c2p1;
        }
    }
    // r2[k] = ||rel[k]||^2 (quad per row)
    {
        const int k = t >> 2, q = t & 3;
        float v = 0.f;
#pragma unroll
        for (int j = 0; j < 4; j++) {
            float4 rv = *(const float4*)&srel[k * PAD + q * 16 + 4 * j];
            v += dot4(rv, rv);
        }
        v += __shfl_xor_sync(0xffffffffu, v, 1);
        v += __shfl_xor_sync(0xffffffffu, v, 2);
        if (q == 0) sr2[k] = v;
    }
    __syncthreads();
    if (t < KNB) {
        sc1[t] = sred1[t] + sred1[64 + t];
        sc2[t] = sred2[t] + sred2[64 + t];
    }

    // ===================== two GAT layers =====================
    for (int layer = 0; layer < 2; layer++) {
        __syncthreads();
        // hs = W1 @ src + b   (row-major W1 from global, L1-hot)
        if (t < D) {
            const float4* row = (const float4*)&g_W1[t * 64];
            const float4* sv = (const float4*)ssrc;
            float a0 = 0.f, a1 = 0.f, a2 = 0.f, a3 = 0.f;
#pragma unroll
            for (int i = 0; i < 16; i += 4) {
                a0 += dot4(row[i + 0], sv[i + 0]);
                a1 += dot4(row[i + 1], sv[i + 1]);
                a2 += dot4(row[i + 2], sv[i + 2]);
                a3 += dot4(row[i + 3], sv[i + 3]);
            }
            shs[t] = ((a0 + a1) + (a2 + a3)) + sb[t];
        }
        __syncthreads();
        // g = W2^T @ hs (rows of g_W2t), s2 = ||hs||^2
        if (t < D) {
            const float4* row = (const float4*)&g_W2t[t * 64];
            const float4* hv = (const float4*)shs;
            float a0 = 0.f, a1 = 0.f, a2 = 0.f, a3 = 0.f;
#pragma unroll
            for (int i = 0; i < 16; i += 4) {
                a0 += dot4(row[i + 0], hv[i + 0]);
                a1 += dot4(row[i + 1], hv[i + 1]);
                a2 += dot4(row[i + 2], hv[i + 2]);
                a3 += dot4(row[i + 3], hv[i + 3]);
            }
            sg[t] = ((a0 + a1) + (a2 + a3));
        } else if (t < 96) {
            int ll = t - 64;
            float v = shs[ll] * shs[ll] + shs[ll + 32] * shs[ll + 32];
#pragma unroll
            for (int s = 16; s; s >>= 1) v += __shfl_xor_sync(0xffffffffu, v, s);
            if (ll == 0) s_s2 = v;
        }
        __syncthreads();
        // dr[k]=<hs,rel[k]>, dh[k]=<g,dst[k]> (quad per row)
        {
            const int k = t >> 2, q = t & 3;
            float dr = 0.f, dh = 0.f;
#pragma unroll
            for (int j = 0; j < 4; j++) {
                int c = q * 16 + 4 * j;
                dr += dot4(*(const float4*)&shs[c], *(const float4*)&srel[k * PAD + c]);
                dh += dot4(*(const float4*)&sg[c],  *(const float4*)&sdst[k * PAD + c]);
            }
            dr += __shfl_xor_sync(0xffffffffu, dr, 1);
            dh += __shfl_xor_sync(0xffffffffu, dh, 1);
            dr += __shfl_xor_sync(0xffffffffu, dr, 2);
            dh += __shfl_xor_sync(0xffffffffu, dh, 2);
            if (q == 0) { sdr[k] = dr; sdh[k] = dh; }
        }
        __syncthreads();
        // logits + masked softmax (warp 0)
        if (t < 32) {
            float e[2];
#pragma unroll
            for (int h = 0; h < 2; h++) {
                int k = t + 32 * h;
                float num = sc1[k] + sdr[k];
                float hn2 = s_s2 + 2.0f * sdh[k] + sc2[k];
                float hn = sqrtf(fmaxf(hn2, 0.0f));
                float rn = sqrtf(sr2[k]);
                float den = fmaxf(hn, 1e-8f) * fmaxf(rn, 1e-8f);
                float ee = num / den;
                ee = (ee < 0.0f) ? 0.2f * ee : ee;
                e[h] = (smask[k] > 0) ? ee : -9e15f;
            }
            float m = fmaxf(e[0], e[1]);
#pragma unroll
            for (int s = 16; s; s >>= 1) m = fmaxf(m, __shfl_xor_sync(0xffffffffu, m, s));
            float x0 = __expf(e[0] - m), x1 = __expf(e[1] - m);
            float sum = x0 + x1;
#pragma unroll
            for (int s = 16; s; s >>= 1) sum += __shfl_xor_sync(0xffffffffu, sum, s);
            float inv = 1.0f / sum;
            satt[t] = x0 * inv; satt[t + 32] = x1 * inv;
        }
        __syncthreads();
        // agg partials: all 256 threads (4 k-groups x 64 cols)
        {
            const int c = t & 63, kg = t >> 6;
            float a = 0.f;
#pragma unroll
            for (int j = 0; j < 16; j++) {
                int k = kg * 16 + j;
                a = fmaf(satt[k], sdst[k * PAD + c], a);
            }
            sagg[kg * 64 + c] = a;
        }
        __syncthreads();
        if (t < D) {
            float o = ((sagg[t] + sagg[64 + t]) + (sagg[128 + t] + sagg[192 + t])) + ssrc[t];
            if (layer == 0) ssrc[t] = o;
            else out[(size_t)n * D + t] = o;
        }
    }
}

static const int SMEM_BYTES = (2 * KNB * PAD) * 4 + 2 * D * PADB * 2;  // 34816 + 18432 = 53248

extern "C" void kernel_launch(void* const* d_in, const int* in_sizes, int n_in,
                              void* d_out, int out_size) {
    const float* src  = (const float*)d_in[0];
    const float* dst  = (const float*)d_in[1];
    const float* rel  = (const float*)d_in[2];
    const float* fcw  = (const float*)d_in[3];
    const float* fcb  = (const float*)d_in[4];
    const int*   mask = (const int*)d_in[5];
    (void)n_in;

    int N = in_sizes[0] / D;   // 50000
    float* outp = (float*)d_out;
    (void)out_size;

    prep_kernel<<<(D * 2 * D + 255) / 256, 256>>>(fcw);

    cudaFuncSetAttribute(kgat_kernel, cudaFuncAttributeMaxDynamicSharedMemorySize, SMEM_BYTES);
    kgat_kernel<<<N, 256, SMEM_BYTES>>>(src, dst, rel, fcb, mask, outp);
}

// round 7
// speedup vs baseline: 1.3077x; 1.3077x over previous
#include <cuda_runtime.h>
#include <cuda_bf16.h>
#include <cstdint>

#define D 64
#define KNB 64
#define PADB 72    // bf16 smem row stride (shorts); bank(4g+tg) distinct -> conflict-free

// ---------------- prepped weights in global ----------------
__device__ float g_W1t[D * D];    // [f][d]: hs matvec, coalesced over d
__device__ float g_W2df[D * D];   // [d][f]: g matvec, coalesced over f
__device__ __align__(16) unsigned short g_Bhi[D * PADB];  // W2 bf16 hi, [d][f] padded
__device__ __align__(16) unsigned short g_Blo[D * PADB];  // W2 bf16 lo residual

__device__ __forceinline__ uint32_t smem_u32(const void* p) {
    uint32_t a;
    asm("{ .reg .u64 t; cvta.to.shared.u64 t, %1; cvt.u32.u64 %0, t; }" : "=r"(a) : "l"(p));
    return a;
}
__device__ __forceinline__ void cp16(uint32_t s, const void* g) {
    asm volatile("cp.async.cg.shared.global [%0], [%1], 16;" :: "r"(s), "l"(g));
}
#define CP_COMMIT_WAIT() do { \
    asm volatile("cp.async.commit_group;" ::: "memory"); \
    asm volatile("cp.async.wait_group 0;" ::: "memory"); } while (0)

#define MMA(ac, A, B0, B1) \
    asm volatile("mma.sync.aligned.m16n8k16.row.col.f32.bf16.bf16.f32 " \
        "{%0,%1,%2,%3}, {%4,%5,%6,%7}, {%8,%9}, {%0,%1,%2,%3};" \
        : "+f"((ac)[0]), "+f"((ac)[1]), "+f"((ac)[2]), "+f"((ac)[3]) \
        : "r"((A)[0]), "r"((A)[1]), "r"((A)[2]), "r"((A)[3]), "r"(B0), "r"(B1))

__device__ __forceinline__ void split2(float2 f, unsigned& hi, unsigned& lo) {
    unsigned u0 = __float_as_uint(f.x), u1 = __float_as_uint(f.y);
    hi = (u0 >> 16) | (u1 & 0xFFFF0000u);
    float l0 = f.x - __uint_as_float(u0 & 0xFFFF0000u);
    float l1 = f.y - __uint_as_float(u1 & 0xFFFF0000u);
    __nv_bfloat162 p = __floats2bfloat162_rn(l0, l1);
    lo = *reinterpret_cast<unsigned*>(&p);
}

// ---------------- prep kernel ----------------
__global__ void prep_kernel(const float* __restrict__ fc_w) {
    int i = blockIdx.x * 256 + threadIdx.x;
    if (i < D * 2 * D) {
        int d = i >> 7, f = i & 127;
        float v = fc_w[i];
        if (f < 64) {
            g_W1t[f * 64 + d] = v;
        } else {
            int f2 = f - 64;
            g_W2df[d * 64 + f2] = v;
            unsigned u = __float_as_uint(v);
            g_Bhi[d * PADB + f2] = (unsigned short)(u >> 16);
            float lo = v - __uint_as_float(u & 0xFFFF0000u);
            g_Blo[d * PADB + f2] = __bfloat16_as_ushort(__float2bfloat16(lo));
        }
    }
}

// ---------------- main fused kernel ----------------
__global__ void __launch_bounds__(256, 4) kgat_kernel(
    const float* __restrict__ src_embs,
    const float* __restrict__ dst_embs,
    const float* __restrict__ rel_embs,
    const float* __restrict__ fc_b,
    const int*   __restrict__ mask,
    float* __restrict__ out)
{
    __shared__ __align__(16) unsigned short sBhi[D * PADB];
    __shared__ __align__(16) unsigned short sBlo[D * PADB];
    __shared__ __align__(16) float ssrc[D], shs[D], sg[D], sb[D];
    __shared__ float sc1[KNB], sc2[KNB], sr2[KNB];
    __shared__ float sdr[KNB], sdh[KNB], satt[KNB];
    __shared__ float sred1[128], sred2[128];
    __shared__ float sagg[8 * D];
    __shared__ int   smask[KNB];
    __shared__ float s_s2;

    const int n = blockIdx.x;
    const int t = threadIdx.x;
    const int w = t >> 5, l = t & 31;
    const int g = l >> 2, tg = l & 3;

    const float* gdst = dst_embs + (size_t)n * (KNB * D);
    const float* grel = rel_embs + (size_t)n * (KNB * D);

    // ---- prologue: stage only B (W2 hi/lo bf16) into smem ----
    {
        const uint32_t bh = smem_u32(sBhi), bl = smem_u32(sBlo);
        for (int i = t; i < D * PADB * 2 / 16; i += 256) {   // 576 chunks of 16B
            cp16(bh + i * 16, ((const float4*)g_Bhi) + i);
            cp16(bl + i * 16, ((const float4*)g_Blo) + i);
        }
    }
    if (t < D) {
        ssrc[t] = src_embs[(size_t)n * D + t];
        sb[t] = fc_b[t];
        smask[t] = mask[(size_t)n * KNB + t];
    }
    CP_COMMIT_WAIT();
    __syncthreads();

    // ============ HMMA GEMM: hd = dst @ W2^T (bf16 hi/lo), A + rel from GLOBAL ============
    {
        const int m0 = (w >> 1) * 16;
        const int nh = w & 1;
        const float* Ab = gdst + (m0 + g) * 64 + 2 * tg;   // lane base (row m0+g)
        float acc[4][4];
#pragma unroll
        for (int i = 0; i < 4; i++)
#pragma unroll
            for (int j = 0; j < 4; j++) acc[i][j] = 0.f;

#pragma unroll
        for (int ks = 0; ks < 4; ks++) {
            const int k0 = ks * 16;
            float2 fA0 = *(const float2*)(Ab + k0);
            float2 fA1 = *(const float2*)(Ab + k0 + 512);       // +8 rows
            float2 fA2 = *(const float2*)(Ab + k0 + 8);
            float2 fA3 = *(const float2*)(Ab + k0 + 520);
            unsigned Ahi[4], Alo[4];
            split2(fA0, Ahi[0], Alo[0]);
            split2(fA1, Ahi[1], Alo[1]);
            split2(fA2, Ahi[2], Alo[2]);
            split2(fA3, Ahi[3], Alo[3]);
#pragma unroll
            for (int nt = 0; nt < 4; nt++) {
                const int n0 = nh * 32 + nt * 8;
                const unsigned short* bh = &sBhi[(n0 + g) * PADB + k0 + 2 * tg];
                const unsigned short* bl = &sBlo[(n0 + g) * PADB + k0 + 2 * tg];
                unsigned Bh0 = *(const unsigned*)bh;
                unsigned Bh1 = *(const unsigned*)(bh + 8);
                unsigned Bl0 = *(const unsigned*)bl;
                unsigned Bl1 = *(const unsigned*)(bl + 8);
                MMA(acc[nt], Ahi, Bh0, Bh1);
                MMA(acc[nt], Alo, Bh0, Bh1);
                MMA(acc[nt], Ahi, Bl0, Bl1);
            }
        }
        // epilogue: c1 = <hd,rel>, c2 = ||hd||^2 per k-row (rel fragments from global)
        const float* Rb = grel + (m0 + g) * 64 + 2 * tg;
        float c1p0 = 0.f, c1p1 = 0.f, c2p0 = 0.f, c2p1 = 0.f;
#pragma unroll
        for (int nt = 0; nt < 4; nt++) {
            const int c = nh * 32 + nt * 8;
            float2 re0 = *(const float2*)(Rb + c);
            float2 re1 = *(const float2*)(Rb + c + 512);
            c1p0 += acc[nt][0] * re0.x + acc[nt][1] * re0.y;
            c1p1 += acc[nt][2] * re1.x + acc[nt][3] * re1.y;
            c2p0 += acc[nt][0] * acc[nt][0] + acc[nt][1] * acc[nt][1];
            c2p1 += acc[nt][2] * acc[nt][2] + acc[nt][3] * acc[nt][3];
        }
        c1p0 += __shfl_xor_sync(0xffffffffu, c1p0, 1);
        c1p1 += __shfl_xor_sync(0xffffffffu, c1p1, 1);
        c2p0 += __shfl_xor_sync(0xffffffffu, c2p0, 1);
        c2p1 += __shfl_xor_sync(0xffffffffu, c2p1, 1);
        c1p0 += __shfl_xor_sync(0xffffffffu, c1p0, 2);
        c1p1 += __shfl_xor_sync(0xffffffffu, c1p1, 2);
        c2p0 += __shfl_xor_sync(0xffffffffu, c2p0, 2);
        c2p1 += __shfl_xor_sync(0xffffffffu, c2p1, 2);
        if (tg == 0) {
            sred1[nh * 64 + m0 + g] = c1p0;
            sred1[nh * 64 + m0 + g + 8] = c1p1;
            sred2[nh * 64 + m0 + g] = c2p0;
            sred2[nh * 64 + m0 + g + 8] = c2p1;
        }
    }
    __syncthreads();
    if (t < KNB) {
        sc1[t] = sred1[t] + sred1[64 + t];
        sc2[t] = sred2[t] + sred2[64 + t];
    }

    // ===================== two GAT layers =====================
    for (int layer = 0; layer < 2; layer++) {
        __syncthreads();
        // hs = W1 @ src + b   (f-major coalesced LDG)
        if (t < D) {
            float a0 = 0.f, a1 = 0.f, a2 = 0.f, a3 = 0.f;
#pragma unroll 4
            for (int f = 0; f < D; f += 4) {
                a0 = fmaf(ssrc[f + 0], g_W1t[(f + 0) * 64 + t], a0);
                a1 = fmaf(ssrc[f + 1], g_W1t[(f + 1) * 64 + t], a1);
                a2 = fmaf(ssrc[f + 2], g_W1t[(f + 2) * 64 + t], a2);
                a3 = fmaf(ssrc[f + 3], g_W1t[(f + 3) * 64 + t], a3);
            }
            shs[t] = ((a0 + a1) + (a2 + a3)) + sb[t];
        }
        __syncthreads();
        // g[f] = sum_d W2[d][f] * hs[d]  (d-major coalesced LDG), s2 by warp 2
        if (t < D) {
            float a0 = 0.f, a1 = 0.f, a2 = 0.f, a3 = 0.f;
#pragma unroll 4
            for (int d = 0; d < D; d += 4) {
                a0 = fmaf(shs[d + 0], g_W2df[(d + 0) * 64 + t], a0);
                a1 = fmaf(shs[d + 1], g_W2df[(d + 1) * 64 + t], a1);
                a2 = fmaf(shs[d + 2], g_W2df[(d + 2) * 64 + t], a2);
                a3 = fmaf(shs[d + 3], g_W2df[(d + 3) * 64 + t], a3);
            }
            sg[t] = ((a0 + a1) + (a2 + a3));
        } else if (t < 96) {
            int ll = t - 64;
            float v = shs[ll] * shs[ll] + shs[ll + 32] * shs[ll + 32];
#pragma unroll
            for (int s = 16; s; s >>= 1) v += __shfl_xor_sync(0xffffffffu, v, s);
            if (ll == 0) s_s2 = v;
        }
        __syncthreads();
        // dots: warp w handles rows k = 8w..8w+7; lane reads cols l, l+32 from GLOBAL
        {
            const float h0 = shs[l], h1 = shs[l + 32];
            const float gg0 = sg[l], gg1 = sg[l + 32];
#pragma unroll
            for (int j = 0; j < 8; j++) {
                const int k = 8 * w + j;
                const float* rr = grel + k * 64;
                const float* dd = gdst + k * 64;
                float r0 = rr[l], r1 = rr[l + 32];
                float d0 = dd[l], d1 = dd[l + 32];
                float dr = h0 * r0 + h1 * r1;
                float dh = gg0 * d0 + gg1 * d1;
                if (layer == 0) {
                    float r2 = r0 * r0 + r1 * r1;
#pragma unroll
                    for (int s = 16; s; s >>= 1) {
                        dr += __shfl_xor_sync(0xffffffffu, dr, s);
                        dh += __shfl_xor_sync(0xffffffffu, dh, s);
                        r2 += __shfl_xor_sync(0xffffffffu, r2, s);
                    }
                    if (l == 0) { sdr[k] = dr; sdh[k] = dh; sr2[k] = r2; }
                } else {
#pragma unroll
                    for (int s = 16; s; s >>= 1) {
                        dr += __shfl_xor_sync(0xffffffffu, dr, s);
                        dh += __shfl_xor_sync(0xffffffffu, dh, s);
                    }
                    if (l == 0) { sdr[k] = dr; sdh[k] = dh; }
                }
            }
        }
        __syncthreads();
        // logits + masked softmax (warp 0)
        if (t < 32) {
            float e[2];
#pragma unroll
            for (int h = 0; h < 2; h++) {
                int k = t + 32 * h;
                float num = sc1[k] + sdr[k];
                float hn2 = s_s2 + 2.0f * sdh[k] + sc2[k];
                float hn = sqrtf(fmaxf(hn2, 0.0f));
                float rn = sqrtf(sr2[k]);
                float den = fmaxf(hn, 1e-8f) * fmaxf(rn, 1e-8f);
                float ee = num / den;
                ee = (ee < 0.0f) ? 0.2f * ee : ee;
                e[h] = (smask[k] > 0) ? ee : -9e15f;
            }
            float m = fmaxf(e[0], e[1]);
#pragma unroll
            for (int s = 16; s; s >>= 1) m = fmaxf(m, __shfl_xor_sync(0xffffffffu, m, s));
            float x0 = __expf(e[0] - m), x1 = __expf(e[1] - m);
            float sum = x0 + x1;
#pragma unroll
            for (int s = 16; s; s >>= 1) sum += __shfl_xor_sync(0xffffffffu, sum, s);
            float inv = 1.0f / sum;
            satt[t] = x0 * inv; satt[t + 32] = x1 * inv;
        }
        __syncthreads();
        // agg: row pattern from GLOBAL dst, per-warp partials, smem combine
        {
            float a0 = 0.f, a1 = 0.f;
#pragma unroll
            for (int j = 0; j < 8; j++) {
                const int k = 8 * w + j;
                const float av = satt[k];
                const float* dd = gdst + k * 64;
                a0 = fmaf(av, dd[l], a0);
                a1 = fmaf(av, dd[l + 32], a1);
            }
            sagg[w * 64 + l] = a0;
            sagg[w * 64 + l + 32] = a1;
        }
        __syncthreads();
        if (t < D) {
            float o = 0.f;
#pragma unroll
            for (int j = 0; j < 8; j++) o += sagg[j * 64 + t];
            o += ssrc[t];
            if (layer == 0) ssrc[t] = o;
            else out[(size_t)n * D + t] = o;
        }
    }
}

extern "C" void kernel_launch(void* const* d_in, const int* in_sizes, int n_in,
                              void* d_out, int out_size) {
    const float* src  = (const float*)d_in[0];
    const float* dst  = (const float*)d_in[1];
    const float* rel  = (const float*)d_in[2];
    const float* fcw  = (const float*)d_in[3];
    const float* fcb  = (const float*)d_in[4];
    const int*   mask = (const int*)d_in[5];
    (void)n_in;

    int N = in_sizes[0] / D;   // 50000
    float* outp = (float*)d_out;
    (void)out_size;

    prep_kernel<<<(D * 2 * D + 255) / 256, 256>>>(fcw);
    kgat_kernel<<<N, 256>>>(src, dst, rel, fcb, mask, outp);
}

// round 8
// speedup vs baseline: 1.3271x; 1.0148x over previous
#include <cuda_runtime.h>
#include <cuda_bf16.h>
#include <cstdint>

#define D 64
#define KNB 64
#define PADB 72    // bf16 smem row stride (shorts); conflict-free fragment reads

// ---------------- prepped weights in global ----------------
__device__ float g_W1t[D * D];    // [f][d]: hs matvec, coalesced over d
__device__ float g_W2df[D * D];   // [d][f]: g matvec, coalesced over f
__device__ __align__(16) unsigned short g_Bhi[D * PADB];  // W2 bf16 hi, [d][f] padded
__device__ __align__(16) unsigned short g_Blo[D * PADB];  // W2 bf16 lo residual

__device__ __forceinline__ uint32_t smem_u32(const void* p) {
    uint32_t a;
    asm("{ .reg .u64 t; cvta.to.shared.u64 t, %1; cvt.u32.u64 %0, t; }" : "=r"(a) : "l"(p));
    return a;
}
__device__ __forceinline__ void cp16(uint32_t s, const void* g) {
    asm volatile("cp.async.cg.shared.global [%0], [%1], 16;" :: "r"(s), "l"(g));
}
#define CP_COMMIT_WAIT() do { \
    asm volatile("cp.async.commit_group;" ::: "memory"); \
    asm volatile("cp.async.wait_group 0;" ::: "memory"); } while (0)

#define MMA(ac, A, B0, B1) \
    asm volatile("mma.sync.aligned.m16n8k16.row.col.f32.bf16.bf16.f32 " \
        "{%0,%1,%2,%3}, {%4,%5,%6,%7}, {%8,%9}, {%0,%1,%2,%3};" \
        : "+f"((ac)[0]), "+f"((ac)[1]), "+f"((ac)[2]), "+f"((ac)[3]) \
        : "r"((A)[0]), "r"((A)[1]), "r"((A)[2]), "r"((A)[3]), "r"(B0), "r"(B1))

__device__ __forceinline__ void split2(float2 f, unsigned& hi, unsigned& lo) {
    unsigned u0 = __float_as_uint(f.x), u1 = __float_as_uint(f.y);
    hi = (u0 >> 16) | (u1 & 0xFFFF0000u);
    float l0 = f.x - __uint_as_float(u0 & 0xFFFF0000u);
    float l1 = f.y - __uint_as_float(u1 & 0xFFFF0000u);
    __nv_bfloat162 p = __floats2bfloat162_rn(l0, l1);
    lo = *reinterpret_cast<unsigned*>(&p);
}
__device__ __forceinline__ float dot4(const float4& a, const float4& b) {
    return a.x * b.x + a.y * b.y + a.z * b.z + a.w * b.w;
}

// ---------------- prep kernel ----------------
__global__ void prep_kernel(const float* __restrict__ fc_w) {
    int i = blockIdx.x * 256 + threadIdx.x;
    if (i < D * 2 * D) {
        int d = i >> 7, f = i & 127;
        float v = fc_w[i];
        if (f < 64) {
            g_W1t[f * 64 + d] = v;
        } else {
            int f2 = f - 64;
            g_W2df[d * 64 + f2] = v;
            unsigned u = __float_as_uint(v);
            g_Bhi[d * PADB + f2] = (unsigned short)(u >> 16);
            float lo = v - __uint_as_float(u & 0xFFFF0000u);
            g_Blo[d * PADB + f2] = __bfloat16_as_ushort(__float2bfloat16(lo));
        }
    }
}

// ---------------- main fused kernel ----------------
__global__ void __launch_bounds__(256, 4) kgat_kernel(
    const float* __restrict__ src_embs,
    const float* __restrict__ dst_embs,
    const float* __restrict__ rel_embs,
    const float* __restrict__ fc_b,
    const int*   __restrict__ mask,
    float* __restrict__ out)
{
    __shared__ __align__(16) unsigned short sBhi[D * PADB];
    __shared__ __align__(16) unsigned short sBlo[D * PADB];
    __shared__ __align__(16) float ssrc[D], shs[D], sg[D], sb[D];
    __shared__ float sc1[KNB], sc2[KNB], sr2[KNB];
    __shared__ float sdr[KNB], sdh[KNB], satt[KNB];
    __shared__ float sred1[128], sred2[128];
    __shared__ float sagg[8 * D];
    __shared__ int   smask[KNB];
    __shared__ float s_s2;

    const int n = blockIdx.x;
    const int t = threadIdx.x;
    const int w = t >> 5, l = t & 31;
    const int g = l >> 2, tg = l & 3;

    const float* gdst = dst_embs + (size_t)n * (KNB * D);
    const float* grel = rel_embs + (size_t)n * (KNB * D);

    // ---- prologue: stage only B (W2 hi/lo bf16) into smem ----
    {
        const uint32_t bh = smem_u32(sBhi), bl = smem_u32(sBlo);
        for (int i = t; i < D * PADB * 2 / 16; i += 256) {   // 576 chunks of 16B
            cp16(bh + i * 16, ((const float4*)g_Bhi) + i);
            cp16(bl + i * 16, ((const float4*)g_Blo) + i);
        }
    }
    if (t < D) {
        ssrc[t] = src_embs[(size_t)n * D + t];
        sb[t] = fc_b[t];
        smask[t] = mask[(size_t)n * KNB + t];
    }
    CP_COMMIT_WAIT();
    __syncthreads();

    // ============ HMMA GEMM: hd = dst @ W2^T (bf16 hi/lo), A + rel from GLOBAL ============
    {
        const int m0 = (w >> 1) * 16;
        const int nh = w & 1;
        const float* Ab = gdst + (m0 + g) * 64 + 2 * tg;
        float acc[4][4];
#pragma unroll
        for (int i = 0; i < 4; i++)
#pragma unroll
            for (int j = 0; j < 4; j++) acc[i][j] = 0.f;

#pragma unroll
        for (int ks = 0; ks < 4; ks++) {
            const int k0 = ks * 16;
            float2 fA0 = *(const float2*)(Ab + k0);
            float2 fA1 = *(const float2*)(Ab + k0 + 512);
            float2 fA2 = *(const float2*)(Ab + k0 + 8);
            float2 fA3 = *(const float2*)(Ab + k0 + 520);
            unsigned Ahi[4], Alo[4];
            split2(fA0, Ahi[0], Alo[0]);
            split2(fA1, Ahi[1], Alo[1]);
            split2(fA2, Ahi[2], Alo[2]);
            split2(fA3, Ahi[3], Alo[3]);
#pragma unroll
            for (int nt = 0; nt < 4; nt++) {
                const int n0 = nh * 32 + nt * 8;
                const unsigned short* bh = &sBhi[(n0 + g) * PADB + k0 + 2 * tg];
                const unsigned short* bl = &sBlo[(n0 + g) * PADB + k0 + 2 * tg];
                unsigned Bh0 = *(const unsigned*)bh;
                unsigned Bh1 = *(const unsigned*)(bh + 8);
                unsigned Bl0 = *(const unsigned*)bl;
                unsigned Bl1 = *(const unsigned*)(bl + 8);
                MMA(acc[nt], Ahi, Bh0, Bh1);
                MMA(acc[nt], Alo, Bh0, Bh1);
                MMA(acc[nt], Ahi, Bl0, Bl1);
            }
        }
        // epilogue: c1 = <hd,rel>, c2 = ||hd||^2 per k-row (rel fragments from global)
        const float* Rb = grel + (m0 + g) * 64 + 2 * tg;
        float c1p0 = 0.f, c1p1 = 0.f, c2p0 = 0.f, c2p1 = 0.f;
#pragma unroll
        for (int nt = 0; nt < 4; nt++) {
            const int c = nh * 32 + nt * 8;
            float2 re0 = *(const float2*)(Rb + c);
            float2 re1 = *(const float2*)(Rb + c + 512);
            c1p0 += acc[nt][0] * re0.x + acc[nt][1] * re0.y;
            c1p1 += acc[nt][2] * re1.x + acc[nt][3] * re1.y;
            c2p0 += acc[nt][0] * acc[nt][0] + acc[nt][1] * acc[nt][1];
            c2p1 += acc[nt][2] * acc[nt][2] + acc[nt][3] * acc[nt][3];
        }
        c1p0 += __shfl_xor_sync(0xffffffffu, c1p0, 1);
        c1p1 += __shfl_xor_sync(0xffffffffu, c1p1, 1);
        c2p0 += __shfl_xor_sync(0xffffffffu, c2p0, 1);
        c2p1 += __shfl_xor_sync(0xffffffffu, c2p1, 1);
        c1p0 += __shfl_xor_sync(0xffffffffu, c1p0, 2);
        c1p1 += __shfl_xor_sync(0xffffffffu, c1p1, 2);
        c2p0 += __shfl_xor_sync(0xffffffffu, c2p0, 2);
        c2p1 += __shfl_xor_sync(0xffffffffu, c2p1, 2);
        if (tg == 0) {
            sred1[nh * 64 + m0 + g] = c1p0;
            sred1[nh * 64 + m0 + g + 8] = c1p1;
            sred2[nh * 64 + m0 + g] = c2p0;
            sred2[nh * 64 + m0 + g + 8] = c2p1;
        }
    }
    // r2[k] = ||rel[k]||^2 once (quad-float4 from global)
    {
        const int k = t >> 2, q = t & 3;
        float v = 0.f;
#pragma unroll
        for (int j = 0; j < 4; j++) {
            float4 rv = *(const float4*)(grel + k * 64 + q * 16 + 4 * j);
            v += dot4(rv, rv);
        }
        v += __shfl_xor_sync(0xffffffffu, v, 1);
        v += __shfl_xor_sync(0xffffffffu, v, 2);
        if (q == 0) sr2[k] = v;
    }
    __syncthreads();
    if (t < KNB) {
        sc1[t] = sred1[t] + sred1[64 + t];
        sc2[t] = sred2[t] + sred2[64 + t];
    }

    // ===================== two GAT layers =====================
    for (int layer = 0; layer < 2; layer++) {
        __syncthreads();
        // hs = W1 @ src + b   (f-major coalesced LDG)
        if (t < D) {
            float a0 = 0.f, a1 = 0.f, a2 = 0.f, a3 = 0.f;
#pragma unroll 4
            for (int f = 0; f < D; f += 4) {
                a0 = fmaf(ssrc[f + 0], g_W1t[(f + 0) * 64 + t], a0);
                a1 = fmaf(ssrc[f + 1], g_W1t[(f + 1) * 64 + t], a1);
                a2 = fmaf(ssrc[f + 2], g_W1t[(f + 2) * 64 + t], a2);
                a3 = fmaf(ssrc[f + 3], g_W1t[(f + 3) * 64 + t], a3);
            }
            shs[t] = ((a0 + a1) + (a2 + a3)) + sb[t];
        }
        __syncthreads();
        // g[f] = sum_d W2[d][f] * hs[d]  (d-major coalesced LDG), s2 by warp 2
        if (t < D) {
            float a0 = 0.f, a1 = 0.f, a2 = 0.f, a3 = 0.f;
#pragma unroll 4
            for (int d = 0; d < D; d += 4) {
                a0 = fmaf(shs[d + 0], g_W2df[(d + 0) * 64 + t], a0);
                a1 = fmaf(shs[d + 1], g_W2df[(d + 1) * 64 + t], a1);
                a2 = fmaf(shs[d + 2], g_W2df[(d + 2) * 64 + t], a2);
                a3 = fmaf(shs[d + 3], g_W2df[(d + 3) * 64 + t], a3);
            }
            sg[t] = ((a0 + a1) + (a2 + a3));
        } else if (t < 96) {
            int ll = t - 64;
            float v = shs[ll] * shs[ll] + shs[ll + 32] * shs[ll + 32];
#pragma unroll
            for (int s = 16; s; s >>= 1) v += __shfl_xor_sync(0xffffffffu, v, s);
            if (ll == 0) s_s2 = v;
        }
        __syncthreads();
        // ---- dots via HMMA: warp (w>>1) = m-tile, (w&1) picks A = rel (dr) or dst (dh)
        // B cols = [hs_hi, hs_lo, g_hi, g_lo, 0,0,0,0]; K-reduction inside MMA -> no shfl
        {
            const int m0 = (w >> 1) * 16;
            const int wA = w & 1;
            const float* Ab = (wA ? gdst : grel) + (m0 + g) * 64 + 2 * tg;
            const float* vecp = (g & 2) ? sg : shs;   // cols 2,3 use g-vector
            const unsigned isLo = g & 1;
            float acc[4] = {0.f, 0.f, 0.f, 0.f};
#pragma unroll
            for (int ks = 0; ks < 4; ks++) {
                const int k0 = ks * 16;
                // B fragment (per-lane build, broadcast LDS)
                float2 v0 = *(const float2*)&vecp[k0 + 2 * tg];
                float2 v1 = *(const float2*)&vecp[k0 + 2 * tg + 8];
                unsigned h0, lo0, h1, lo1;
                split2(v0, h0, lo0);
                split2(v1, h1, lo1);
                unsigned B0 = isLo ? lo0 : h0;
                unsigned B1 = isLo ? lo1 : h1;
                if (g >= 4) { B0 = 0u; B1 = 0u; }
                // A fragments (hi/lo), both accumulated -> (A_hi+A_lo)*(B)
                float2 fA0 = *(const float2*)(Ab + k0);
                float2 fA1 = *(const float2*)(Ab + k0 + 512);
                float2 fA2 = *(const float2*)(Ab + k0 + 8);
                float2 fA3 = *(const float2*)(Ab + k0 + 520);
                unsigned Ahi[4], Alo[4];
                split2(fA0, Ahi[0], Alo[0]);
                split2(fA1, Ahi[1], Alo[1]);
                split2(fA2, Ahi[2], Alo[2]);
                split2(fA3, Ahi[3], Alo[3]);
                MMA(acc, Ahi, B0, B1);
                MMA(acc, Alo, B0, B1);
            }
            // acc rows (m0+g, m0+g+8), cols (2tg, 2tg+1).
            // tg==0 -> cols 0+1 = <row, hs>; tg==1 -> cols 2+3 = <row, g>
            float v01 = acc[0] + acc[1];
            float v23 = acc[2] + acc[3];
            if (wA == 0 && tg == 0) { sdr[m0 + g] = v01; sdr[m0 + g + 8] = v23; }
            if (wA == 1 && tg == 1) { sdh[m0 + g] = v01; sdh[m0 + g + 8] = v23; }
        }
        __syncthreads();
        // logits + masked softmax (warp 0)
        if (t < 32) {
            float e[2];
#pragma unroll
            for (int h = 0; h < 2; h++) {
                int k = t + 32 * h;
                float num = sc1[k] + sdr[k];
                float hn2 = s_s2 + 2.0f * sdh[k] + sc2[k];
                float hn = sqrtf(fmaxf(hn2, 0.0f));
                float rn = sqrtf(sr2[k]);
                float den = fmaxf(hn, 1e-8f) * fmaxf(rn, 1e-8f);
                float ee = num / den;
                ee = (ee < 0.0f) ? 0.2f * ee : ee;
                e[h] = (smask[k] > 0) ? ee : -9e15f;
            }
            float m = fmaxf(e[0], e[1]);
#pragma unroll
            for (int s = 16; s; s >>= 1) m = fmaxf(m, __shfl_xor_sync(0xffffffffu, m, s));
            float x0 = __expf(e[0] - m), x1 = __expf(e[1] - m);
            float sum = x0 + x1;
#pragma unroll
            for (int s = 16; s; s >>= 1) sum += __shfl_xor_sync(0xffffffffu, sum, s);
            float inv = 1.0f / sum;
            satt[t] = x0 * inv; satt[t + 32] = x1 * inv;
        }
        __syncthreads();
        // agg: row pattern from GLOBAL dst, per-warp partials, smem combine
        {
            float a0 = 0.f, a1 = 0.f;
#pragma unroll
            for (int j = 0; j < 8; j++) {
                const int k = 8 * w + j;
                const float av = satt[k];
                const float* dd = gdst + k * 64;
                a0 = fmaf(av, dd[l], a0);
                a1 = fmaf(av, dd[l + 32], a1);
            }
            sagg[w * 64 + l] = a0;
            sagg[w * 64 + l + 32] = a1;
        }
        __syncthreads();
        if (t < D) {
            float o = 0.f;
#pragma unroll
            for (int j = 0; j < 8; j++) o += sagg[j * 64 + t];
            o += ssrc[t];
            if (layer == 0) ssrc[t] = o;
            else out[(size_t)n * D + t] = o;
        }
    }
}

extern "C" void kernel_launch(void* const* d_in, const int* in_sizes, int n_in,
                              void* d_out, int out_size) {
    const float* src  = (const float*)d_in[0];
    const float* dst  = (const float*)d_in[1];
    const float* rel  = (const float*)d_in[2];
    const float* fcw  = (const float*)d_in[3];
    const float* fcb  = (const float*)d_in[4];
    const int*   mask = (const int*)d_in[5];
    (void)n_in;

    int N = in_sizes[0] / D;   // 50000
    float* outp = (float*)d_out;
    (void)out_size;

    prep_kernel<<<(D * 2 * D + 255) / 256, 256>>>(fcw);
    kgat_kernel<<<N, 256>>>(src, dst, rel, fcb, mask, outp);
}

// round 9
// speedup vs baseline: 1.6353x; 1.2323x over previous
#include <cuda_runtime.h>
#include <cuda_bf16.h>
#include <cstdint>

#define D 64
#define KNB 64

// ---------------- packed weights in global (prep once) ----------------
__device__ __align__(16) uint4 g_BW2[1024];   // GEMM B frags: [n*16+ks*4+tg] = {Bh0,Bh1,Bl0,Bl1}
__device__ __align__(16) uint4 g_AW1hi[512];  // hs matvec A frags: [(mi*4+ks)*32+l]
__device__ __align__(16) uint4 g_AW1lo[512];
__device__ __align__(16) uint4 g_AW2hi[512];  // g matvec A frags (W2^T)
__device__ __align__(16) uint4 g_AW2lo[512];

#define MMA(ac, A, B0, B1) \
    asm volatile("mma.sync.aligned.m16n8k16.row.col.f32.bf16.bf16.f32 " \
        "{%0,%1,%2,%3}, {%4,%5,%6,%7}, {%8,%9}, {%0,%1,%2,%3};" \
        : "+f"((ac)[0]), "+f"((ac)[1]), "+f"((ac)[2]), "+f"((ac)[3]) \
        : "r"((A)[0]), "r"((A)[1]), "r"((A)[2]), "r"((A)[3]), "r"(B0), "r"(B1))

__device__ __forceinline__ void split2(float2 f, unsigned& hi, unsigned& lo) {
    unsigned u0 = __float_as_uint(f.x), u1 = __float_as_uint(f.y);
    hi = (u0 >> 16) | (u1 & 0xFFFF0000u);
    float l0 = f.x - __uint_as_float(u0 & 0xFFFF0000u);
    float l1 = f.y - __uint_as_float(u1 & 0xFFFF0000u);
    __nv_bfloat162 p = __floats2bfloat162_rn(l0, l1);
    lo = *reinterpret_cast<unsigned*>(&p);
}

// ---------------- prep kernel: pack all weight fragments ----------------
__global__ void prep_kernel(const float* __restrict__ fc_w) {
    int idx = blockIdx.x * 256 + threadIdx.x;
    if (idx < 1024) {
        // GEMM B chunk: n = hd-col row of W2, B[k=f][n] = W2[n][f] = fc_w[n*128+64+f]
        int n = idx >> 4, ks = (idx >> 2) & 3, tg = idx & 3;
        int k0 = ks * 16, c0 = k0 + 2 * tg, c1 = c0 + 8;
        const float* Wn = fc_w + n * 128 + 64;
        uint4 hi, lo;
        split2(make_float2(Wn[c0], Wn[c0 + 1]), hi.x, lo.x);
        split2(make_float2(Wn[c1], Wn[c1 + 1]), hi.y, lo.y);
        g_BW2[idx] = make_uint4(hi.x, hi.y, lo.x, lo.y);
    } else if (idx < 2048) {
        int j = idx - 1024;
        int which = j >> 9;            // 0 = W1 (hs), 1 = W2^T (g)
        int jj = j & 511;
        int mi = jj >> 7, ks = (jj >> 5) & 3, l = jj & 31;
        int g = l >> 2, tg = l & 3;
        int ra = mi * 16 + g, rb = ra + 8;
        int c0 = ks * 16 + 2 * tg, c1 = c0 + 8;
        // A[m][k]: W1: fc_w[m*128+k];  W2^T: fc_w[k*128+64+m]
        float a00, a01, b00, b01, a10, a11, b10, b11;
        if (which == 0) {
            a00 = fc_w[ra * 128 + c0]; a01 = fc_w[ra * 128 + c0 + 1];
            b00 = fc_w[rb * 128 + c0]; b01 = fc_w[rb * 128 + c0 + 1];
            a10 = fc_w[ra * 128 + c1]; a11 = fc_w[ra * 128 + c1 + 1];
            b10 = fc_w[rb * 128 + c1]; b11 = fc_w[rb * 128 + c1 + 1];
        } else {
            a00 = fc_w[c0 * 128 + 64 + ra]; a01 = fc_w[(c0 + 1) * 128 + 64 + ra];
            b00 = fc_w[c0 * 128 + 64 + rb]; b01 = fc_w[(c0 + 1) * 128 + 64 + rb];
            a10 = fc_w[c1 * 128 + 64 + ra]; a11 = fc_w[(c1 + 1) * 128 + 64 + ra];
            b10 = fc_w[c1 * 128 + 64 + rb]; b11 = fc_w[(c1 + 1) * 128 + 64 + rb];
        }
        uint4 hi, lo;
        split2(make_float2(a00, a01), hi.x, lo.x);
        split2(make_float2(b00, b01), hi.y, lo.y);
        split2(make_float2(a10, a11), hi.z, lo.z);
        split2(make_float2(b10, b11), hi.w, lo.w);
        if (which == 0) { g_AW1hi[jj] = hi; g_AW1lo[jj] = lo; }
        else            { g_AW2hi[jj] = hi; g_AW2lo[jj] = lo; }
    }
}

// ---------------- main fused kernel: 128 threads, 4 warps ----------------
__global__ void __launch_bounds__(128, 8) kgat_kernel(
    const float* __restrict__ src_embs,
    const float* __restrict__ dst_embs,
    const float* __restrict__ rel_embs,
    const float* __restrict__ fc_b,
    const int*   __restrict__ mask,
    float* __restrict__ out)
{
    __shared__ __align__(16) float ssrc[D], shs[D], sg[D], sb[D];
    __shared__ float sc1[KNB], sc2[KNB], sr2[KNB];
    __shared__ float sdr[KNB], sdh[KNB], satt[KNB];
    __shared__ float sagg[4 * D];
    __shared__ int   smask[KNB];

    const int n = blockIdx.x;
    const int t = threadIdx.x;
    const int w = t >> 5, l = t & 31;
    const int g = l >> 2, tg = l & 3;

    const float* gdst = dst_embs + (size_t)n * (KNB * D);
    const float* grel = rel_embs + (size_t)n * (KNB * D);

    if (t < D) {
        ssrc[t] = src_embs[(size_t)n * D + t];
        sb[t] = fc_b[t];
        smask[t] = mask[(size_t)n * KNB + t];
    }

    // ============ GEMM: hd = dst @ W2^T; fused c1/c2/r2 epilogue ============
    {
        const int m0 = w * 16;
        const float* Ab = gdst + (m0 + g) * 64 + 2 * tg;
        float acc[8][4];
#pragma unroll
        for (int i = 0; i < 8; i++)
#pragma unroll
            for (int j = 0; j < 4; j++) acc[i][j] = 0.f;

#pragma unroll
        for (int ks = 0; ks < 4; ks++) {
            const int k0 = ks * 16;
            float2 fA0 = *(const float2*)(Ab + k0);
            float2 fA1 = *(const float2*)(Ab + k0 + 512);
            float2 fA2 = *(const float2*)(Ab + k0 + 8);
            float2 fA3 = *(const float2*)(Ab + k0 + 520);
            unsigned Ahi[4], Alo[4];
            split2(fA0, Ahi[0], Alo[0]);
            split2(fA1, Ahi[1], Alo[1]);
            split2(fA2, Ahi[2], Alo[2]);
            split2(fA3, Ahi[3], Alo[3]);
#pragma unroll
            for (int nt = 0; nt < 8; nt++) {
                uint4 Bc = g_BW2[(nt * 8 + g) * 16 + ks * 4 + tg];
                MMA(acc[nt], Ahi, Bc.x, Bc.y);
                MMA(acc[nt], Alo, Bc.x, Bc.y);
                MMA(acc[nt], Ahi, Bc.z, Bc.w);
            }
        }
        // epilogue: per-row c1 = <hd,rel>, c2 = ||hd||^2, r2 = ||rel||^2
        const float* Rb = grel + (m0 + g) * 64 + 2 * tg;
        float c1p0 = 0.f, c1p1 = 0.f, c2p0 = 0.f, c2p1 = 0.f, r2p0 = 0.f, r2p1 = 0.f;
#pragma unroll
        for (int nt = 0; nt < 8; nt++) {
            const int c = nt * 8;
            float2 re0 = *(const float2*)(Rb + c);
            float2 re1 = *(const float2*)(Rb + c + 512);
            c1p0 += acc[nt][0] * re0.x + acc[nt][1] * re0.y;
            c1p1 += acc[nt][2] * re1.x + acc[nt][3] * re1.y;
            c2p0 += acc[nt][0] * acc[nt][0] + acc[nt][1] * acc[nt][1];
            c2p1 += acc[nt][2] * acc[nt][2] + acc[nt][3] * acc[nt][3];
            r2p0 += re0.x * re0.x + re0.y * re0.y;
            r2p1 += re1.x * re1.x + re1.y * re1.y;
        }
#pragma unroll
        for (int s = 1; s < 4; s <<= 1) {
            c1p0 += __shfl_xor_sync(0xffffffffu, c1p0, s);
            c1p1 += __shfl_xor_sync(0xffffffffu, c1p1, s);
            c2p0 += __shfl_xor_sync(0xffffffffu, c2p0, s);
            c2p1 += __shfl_xor_sync(0xffffffffu, c2p1, s);
            r2p0 += __shfl_xor_sync(0xffffffffu, r2p0, s);
            r2p1 += __shfl_xor_sync(0xffffffffu, r2p1, s);
        }
        if (tg == 0) {
            sc1[m0 + g] = c1p0; sc1[m0 + g + 8] = c1p1;
            sc2[m0 + g] = c2p0; sc2[m0 + g + 8] = c2p1;
            sr2[m0 + g] = r2p0; sr2[m0 + g + 8] = r2p1;
        }
    }
    __syncthreads();

    // ===================== two GAT layers =====================
    for (int layer = 0; layer < 2; layer++) {
        // ---- hs = W1 @ src + b  via MMA (A = packed W1 frags, B = [src_hi, src_lo]) ----
        {
            float acc[4] = {0.f, 0.f, 0.f, 0.f};
#pragma unroll
            for (int ks = 0; ks < 4; ks++) {
                const int k0 = ks * 16;
                float2 v0 = *(const float2*)&ssrc[k0 + 2 * tg];
                float2 v1 = *(const float2*)&ssrc[k0 + 2 * tg + 8];
                unsigned h0, lo0, h1, lo1;
                split2(v0, h0, lo0);
                split2(v1, h1, lo1);
                unsigned B0 = (g == 0) ? h0 : (g == 1) ? lo0 : 0u;
                unsigned B1 = (g == 0) ? h1 : (g == 1) ? lo1 : 0u;
                uint4 Ah = g_AW1hi[(w * 4 + ks) * 32 + l];
                uint4 Al = g_AW1lo[(w * 4 + ks) * 32 + l];
                MMA(acc, ((unsigned*)&Ah), B0, B1);
                MMA(acc, ((unsigned*)&Al), B0, B1);
            }
            if (tg == 0) {
                shs[w * 16 + g] = acc[0] + acc[1] + sb[w * 16 + g];
                shs[w * 16 + g + 8] = acc[2] + acc[3] + sb[w * 16 + g + 8];
            }
        }
        __syncthreads();
        // ---- g = W2^T @ hs via MMA ----
        {
            float acc[4] = {0.f, 0.f, 0.f, 0.f};
#pragma unroll
            for (int ks = 0; ks < 4; ks++) {
                const int k0 = ks * 16;
                float2 v0 = *(const float2*)&shs[k0 + 2 * tg];
                float2 v1 = *(const float2*)&shs[k0 + 2 * tg + 8];
                unsigned h0, lo0, h1, lo1;
                split2(v0, h0, lo0);
                split2(v1, h1, lo1);
                unsigned B0 = (g == 0) ? h0 : (g == 1) ? lo0 : 0u;
                unsigned B1 = (g == 0) ? h1 : (g == 1) ? lo1 : 0u;
                uint4 Ah = g_AW2hi[(w * 4 + ks) * 32 + l];
                uint4 Al = g_AW2lo[(w * 4 + ks) * 32 + l];
                MMA(acc, ((unsigned*)&Ah), B0, B1);
                MMA(acc, ((unsigned*)&Al), B0, B1);
            }
            if (tg == 0) {
                sg[w * 16 + g] = acc[0] + acc[1];
                sg[w * 16 + g + 8] = acc[2] + acc[3];
            }
        }
        __syncthreads();
        // ---- dots via MMA: B cols [hs_hi, hs_lo, g_hi, g_lo]; A = rel (dr), A = dst (dh) ----
        {
            const int m0 = w * 16;
            const float* Ar = grel + (m0 + g) * 64 + 2 * tg;
            const float* Ad = gdst + (m0 + g) * 64 + 2 * tg;
            const float* vecp = (g & 2) ? sg : shs;
            const unsigned isLo = g & 1;
            float accR[4] = {0.f, 0.f, 0.f, 0.f};
            float accD[4] = {0.f, 0.f, 0.f, 0.f};
#pragma unroll
            for (int ks = 0; ks < 4; ks++) {
                const int k0 = ks * 16;
                float2 v0 = *(const float2*)&vecp[k0 + 2 * tg];
                float2 v1 = *(const float2*)&vecp[k0 + 2 * tg + 8];
                unsigned h0, lo0, h1, lo1;
                split2(v0, h0, lo0);
                split2(v1, h1, lo1);
                unsigned B0 = isLo ? lo0 : h0;
                unsigned B1 = isLo ? lo1 : h1;
                if (g >= 4) { B0 = 0u; B1 = 0u; }
                unsigned Ahi[4], Alo[4];
                float2 fR0 = *(const float2*)(Ar + k0);
                float2 fR1 = *(const float2*)(Ar + k0 + 512);
                float2 fR2 = *(const float2*)(Ar + k0 + 8);
                float2 fR3 = *(const float2*)(Ar + k0 + 520);
                split2(fR0, Ahi[0], Alo[0]);
                split2(fR1, Ahi[1], Alo[1]);
                split2(fR2, Ahi[2], Alo[2]);
                split2(fR3, Ahi[3], Alo[3]);
                MMA(accR, Ahi, B0, B1);
                MMA(accR, Alo, B0, B1);
                float2 fD0 = *(const float2*)(Ad + k0);
                float2 fD1 = *(const float2*)(Ad + k0 + 512);
                float2 fD2 = *(const float2*)(Ad + k0 + 8);
                float2 fD3 = *(const float2*)(Ad + k0 + 520);
                split2(fD0, Ahi[0], Alo[0]);
                split2(fD1, Ahi[1], Alo[1]);
                split2(fD2, Ahi[2], Alo[2]);
                split2(fD3, Ahi[3], Alo[3]);
                MMA(accD, Ahi, B0, B1);
                MMA(accD, Alo, B0, B1);
            }
            if (tg == 0) { sdr[m0 + g] = accR[0] + accR[1]; sdr[m0 + g + 8] = accR[2] + accR[3]; }
            if (tg == 1) { sdh[m0 + g] = accD[0] + accD[1]; sdh[m0 + g + 8] = accD[2] + accD[3]; }
        }
        __syncthreads();
        // ---- logits + masked softmax (warp 0; s2 computed inline) ----
        if (t < 32) {
            float v = shs[t] * shs[t] + shs[t + 32] * shs[t + 32];
#pragma unroll
            for (int s = 16; s; s >>= 1) v += __shfl_xor_sync(0xffffffffu, v, s);
            const float s2 = v;
            float e[2];
#pragma unroll
            for (int h = 0; h < 2; h++) {
                int k = t + 32 * h;
                float num = sc1[k] + sdr[k];
                float hn2 = s2 + 2.0f * sdh[k] + sc2[k];
                float hn = sqrtf(fmaxf(hn2, 0.0f));
                float rn = sqrtf(sr2[k]);
                float den = fmaxf(hn, 1e-8f) * fmaxf(rn, 1e-8f);
                float ee = num / den;
                ee = (ee < 0.0f) ? 0.2f * ee : ee;
                e[h] = (smask[k] > 0) ? ee : -9e15f;
            }
            float m = fmaxf(e[0], e[1]);
#pragma unroll
            for (int s = 16; s; s >>= 1) m = fmaxf(m, __shfl_xor_sync(0xffffffffu, m, s));
            float x0 = __expf(e[0] - m), x1 = __expf(e[1] - m);
            float sum = x0 + x1;
#pragma unroll
            for (int s = 16; s; s >>= 1) sum += __shfl_xor_sync(0xffffffffu, sum, s);
            float inv = 1.0f / sum;
            satt[t] = x0 * inv; satt[t + 32] = x1 * inv;
        }
        __syncthreads();
        // ---- agg: warp w handles rows 16w..16w+15, coalesced global rows ----
        {
            float a0 = 0.f, a1 = 0.f;
#pragma unroll
            for (int j = 0; j < 16; j++) {
                const int k = 16 * w + j;
                const float av = satt[k];
                const float* dd = gdst + k * 64;
                a0 = fmaf(av, dd[l], a0);
                a1 = fmaf(av, dd[l + 32], a1);
            }
            sagg[w * 64 + l] = a0;
            sagg[w * 64 + l + 32] = a1;
        }
        __syncthreads();
        if (t < D) {
            float o = (sagg[t] + sagg[64 + t]) + (sagg[128 + t] + sagg[192 + t]) + ssrc[t];
            if (layer == 0) ssrc[t] = o;
            else out[(size_t)n * D + t] = o;
        }
        __syncthreads();
    }
}

extern "C" void kernel_launch(void* const* d_in, const int* in_sizes, int n_in,
                              void* d_out, int out_size) {
    const float* src  = (const float*)d_in[0];
    const float* dst  = (const float*)d_in[1];
    const float* rel  = (const float*)d_in[2];
    const float* fcw  = (const float*)d_in[3];
    const float* fcb  = (const float*)d_in[4];
    const int*   mask = (const int*)d_in[5];
    (void)n_in;

    int N = in_sizes[0] / D;   // 50000
    float* outp = (float*)d_out;
    (void)out_size;

    prep_kernel<<<8, 256>>>(fcw);
    kgat_kernel<<<N, 128>>>(src, dst, rel, fcb, mask, outp);
}

// round 10
// speedup vs baseline: 1.9688x; 1.2039x over previous
#include <cuda_runtime.h>
#include <cuda_bf16.h>
#include <cstdint>

#define D 64
#define KNB 64
#define PADB 72    // bf16 smem row stride in shorts (144B): ldmatrix conflict-free

// ---------------- packed weights in global (prep once) ----------------
__device__ __align__(16) uint4 g_BW2[1024];   // GEMM B frags, lane-consecutive: [(nt*4+ks)*32 + l]
__device__ __align__(16) uint4 g_AW1hi[512];  // hs matvec A frags: [(mi*4+ks)*32+l]
__device__ __align__(16) uint4 g_AW1lo[512];
__device__ __align__(16) uint4 g_AW2hi[512];  // g matvec A frags (W2^T)
__device__ __align__(16) uint4 g_AW2lo[512];

#define MMA(ac, A, B0, B1) \
    asm volatile("mma.sync.aligned.m16n8k16.row.col.f32.bf16.bf16.f32 " \
        "{%0,%1,%2,%3}, {%4,%5,%6,%7}, {%8,%9}, {%0,%1,%2,%3};" \
        : "+f"((ac)[0]), "+f"((ac)[1]), "+f"((ac)2 ? (ac)[2] : (ac)[2]), "+f"((ac)[3]) \
        : "r"((A)[0]), "r"((A)[1]), "r"((A)[2]), "r"((A)[3]), "r"(B0), "r"(B1))
#undef MMA
#define MMA(ac, A, B0, B1) \
    asm volatile("mma.sync.aligned.m16n8k16.row.col.f32.bf16.bf16.f32 " \
        "{%0,%1,%2,%3}, {%4,%5,%6,%7}, {%8,%9}, {%0,%1,%2,%3};" \
        : "+f"((ac)[0]), "+f"((ac)[1]), "+f"((ac)[2]), "+f"((ac)[3]) \
        : "r"((A)[0]), "r"((A)[1]), "r"((A)[2]), "r"((A)[3]), "r"(B0), "r"(B1))

__device__ __forceinline__ uint32_t smem_u32(const void* p) {
    uint32_t a;
    asm("{ .reg .u64 t; cvta.to.shared.u64 t, %1; cvt.u32.u64 %0, t; }" : "=r"(a) : "l"(p));
    return a;
}
__device__ __forceinline__ void ldmat4(unsigned r[4], uint32_t addr) {
    asm volatile("ldmatrix.sync.aligned.m8n8.x4.shared.b16 {%0,%1,%2,%3}, [%4];"
        : "=r"(r[0]), "=r"(r[1]), "=r"(r[2]), "=r"(r[3]) : "r"(addr));
}
__device__ __forceinline__ void split2(float2 f, unsigned& hi, unsigned& lo) {
    unsigned u0 = __float_as_uint(f.x), u1 = __float_as_uint(f.y);
    hi = (u0 >> 16) | (u1 & 0xFFFF0000u);
    float l0 = f.x - __uint_as_float(u0 & 0xFFFF0000u);
    float l1 = f.y - __uint_as_float(u1 & 0xFFFF0000u);
    __nv_bfloat162 p = __floats2bfloat162_rn(l0, l1);
    lo = *reinterpret_cast<unsigned*>(&p);
}
__device__ __forceinline__ float2 bfrecon(unsigned h, unsigned lo) {
    float2 a = __bfloat1622float2(*reinterpret_cast<__nv_bfloat162*>(&h));
    float2 b = __bfloat1622float2(*reinterpret_cast<__nv_bfloat162*>(&lo));
    return make_float2(a.x + b.x, a.y + b.y);
}
__device__ __forceinline__ float dot4(const float4& a, const float4& b) {
    return a.x * b.x + a.y * b.y + a.z * b.z + a.w * b.w;
}

// ---------------- prep kernel ----------------
__global__ void prep_kernel(const float* __restrict__ fc_w) {
    int idx = blockIdx.x * 256 + threadIdx.x;
    if (idx < 1024) {
        // lane-consecutive layout: s = (nt*4+ks)*32 + (g*4+tg)
        int nt = idx >> 7, ks = (idx >> 5) & 3, g = (idx >> 2) & 7, tg = idx & 3;
        int nn = nt * 8 + g;
        int c0 = ks * 16 + 2 * tg, c1 = c0 + 8;
        const float* Wn = fc_w + nn * 128 + 64;
        unsigned hx, lx, hy, ly;
        split2(make_float2(Wn[c0], Wn[c0 + 1]), hx, lx);
        split2(make_float2(Wn[c1], Wn[c1 + 1]), hy, ly);
        g_BW2[idx] = make_uint4(hx, hy, lx, ly);
    } else if (idx < 2048) {
        int j = idx - 1024;
        int which = j >> 9;
        int jj = j & 511;
        int mi = jj >> 7, ks = (jj >> 5) & 3, l = jj & 31;
        int g = l >> 2, tg = l & 3;
        int ra = mi * 16 + g, rb = ra + 8;
        int c0 = ks * 16 + 2 * tg, c1 = c0 + 8;
        float a00, a01, b00, b01, a10, a11, b10, b11;
        if (which == 0) {
            a00 = fc_w[ra * 128 + c0]; a01 = fc_w[ra * 128 + c0 + 1];
            b00 = fc_w[rb * 128 + c0]; b01 = fc_w[rb * 128 + c0 + 1];
            a10 = fc_w[ra * 128 + c1]; a11 = fc_w[ra * 128 + c1 + 1];
            b10 = fc_w[rb * 128 + c1]; b11 = fc_w[rb * 128 + c1 + 1];
        } else {
            a00 = fc_w[c0 * 128 + 64 + ra]; a01 = fc_w[(c0 + 1) * 128 + 64 + ra];
            b00 = fc_w[c0 * 128 + 64 + rb]; b01 = fc_w[(c0 + 1) * 128 + 64 + rb];
            a10 = fc_w[c1 * 128 + 64 + ra]; a11 = fc_w[(c1 + 1) * 128 + 64 + ra];
            b10 = fc_w[c1 * 128 + 64 + rb]; b11 = fc_w[(c1 + 1) * 128 + 64 + rb];
        }
        uint4 hi, lo;
        split2(make_float2(a00, a01), hi.x, lo.x);
        split2(make_float2(b00, b01), hi.y, lo.y);
        split2(make_float2(a10, a11), hi.z, lo.z);
        split2(make_float2(b10, b11), hi.w, lo.w);
        if (which == 0) { g_AW1hi[jj] = hi; g_AW1lo[jj] = lo; }
        else            { g_AW2hi[jj] = hi; g_AW2lo[jj] = lo; }
    }
}

// ---------------- main fused kernel: 128 threads, 4 warps ----------------
__global__ void __launch_bounds__(128, 5) kgat_kernel(
    const float* __restrict__ src_embs,
    const float* __restrict__ dst_embs,
    const float* __restrict__ rel_embs,
    const float* __restrict__ fc_b,
    const int*   __restrict__ mask,
    float* __restrict__ out)
{
    __shared__ __align__(16) unsigned short sDhi[D * PADB];
    __shared__ __align__(16) unsigned short sDlo[D * PADB];
    __shared__ __align__(16) unsigned short sRhi[D * PADB];
    __shared__ __align__(16) unsigned short sRlo[D * PADB];
    __shared__ __align__(16) float ssrc[D], shs[D], sg[D], sb[D];
    __shared__ float sc1[KNB], sc2[KNB], sr2[KNB];
    __shared__ float sdr[KNB], sdh[KNB], satt[KNB];
    __shared__ float sagg[4 * D];
    __shared__ int   smask[KNB];

    const int n = blockIdx.x;
    const int t = threadIdx.x;
    const int w = t >> 5, l = t & 31;
    const int g = l >> 2, tg = l & 3;

    const float* gdst = dst_embs + (size_t)n * (KNB * D);
    const float* grel = rel_embs + (size_t)n * (KNB * D);

    if (t < D) {
        ssrc[t] = src_embs[(size_t)n * D + t];
        sb[t] = fc_b[t];
        smask[t] = mask[(size_t)n * KNB + t];
    }

    // ---- prologue: split dst/rel into bf16 hi/lo smem; fold in r2 ----
    {
        const float4* gd4 = (const float4*)gdst;
        const float4* gr4 = (const float4*)grel;
#pragma unroll
        for (int j = 0; j < 8; j++) {
            int i = t + 128 * j;
            int row = i >> 4, c4 = i & 15;
            float4 dv = gd4[i];
            unsigned h0, l0, h1, l1;
            split2(make_float2(dv.x, dv.y), h0, l0);
            split2(make_float2(dv.z, dv.w), h1, l1);
            *(uint2*)&sDhi[row * PADB + c4 * 4] = make_uint2(h0, h1);
            *(uint2*)&sDlo[row * PADB + c4 * 4] = make_uint2(l0, l1);
            float4 rv = gr4[i];
            split2(make_float2(rv.x, rv.y), h0, l0);
            split2(make_float2(rv.z, rv.w), h1, l1);
            *(uint2*)&sRhi[row * PADB + c4 * 4] = make_uint2(h0, h1);
            *(uint2*)&sRlo[row * PADB + c4 * 4] = make_uint2(l0, l1);
            float r2p = dot4(rv, rv);
            r2p += __shfl_xor_sync(0xffffffffu, r2p, 1);
            r2p += __shfl_xor_sync(0xffffffffu, r2p, 2);
            r2p += __shfl_xor_sync(0xffffffffu, r2p, 4);
            r2p += __shfl_xor_sync(0xffffffffu, r2p, 8);
            if ((l & 15) == 0) sr2[row] = r2p;
        }
    }
    __syncthreads();

    const uint32_t aDhi = smem_u32(sDhi), aDlo = smem_u32(sDlo);
    const uint32_t aRhi = smem_u32(sRhi), aRlo = smem_u32(sRlo);
    const int m0 = w * 16;
    // ldmatrix lane address: rows m0..m0+15, 16-col chunk at byte colB
    const uint32_t lmrow = (uint32_t)(m0 + (l & 15)) * (PADB * 2) + (uint32_t)(l >> 4) * 16;

    // ============ GEMM: hd = dst @ W2^T; fused c1/c2 epilogue ============
    {
        float acc[8][4];
#pragma unroll
        for (int i = 0; i < 8; i++)
#pragma unroll
            for (int j = 0; j < 4; j++) acc[i][j] = 0.f;

#pragma unroll
        for (int ks = 0; ks < 4; ks++) {
            unsigned Ahi[4], Alo[4];
            ldmat4(Ahi, aDhi + lmrow + ks * 32);
            ldmat4(Alo, aDlo + lmrow + ks * 32);
#pragma unroll
            for (int nt = 0; nt < 8; nt++) {
                uint4 Bc = g_BW2[((nt * 4 + ks) << 5) + l];
                MMA(acc[nt], Ahi, Bc.x, Bc.y);
                MMA(acc[nt], Alo, Bc.x, Bc.y);
                MMA(acc[nt], Ahi, Bc.z, Bc.w);
            }
        }
        // epilogue: rel fragments via ldmatrix (hi+lo reconstruct)
        float c1p0 = 0.f, c1p1 = 0.f, c2p0 = 0.f, c2p1 = 0.f;
#pragma unroll
        for (int cc = 0; cc < 4; cc++) {
            unsigned Rh[4], Rl[4];
            ldmat4(Rh, aRhi + lmrow + cc * 32);
            ldmat4(Rl, aRlo + lmrow + cc * 32);
            float2 e00 = bfrecon(Rh[0], Rl[0]);   // row g,   nt=2cc
            float2 e01 = bfrecon(Rh[1], Rl[1]);   // row g+8, nt=2cc
            float2 e10 = bfrecon(Rh[2], Rl[2]);   // row g,   nt=2cc+1
            float2 e11 = bfrecon(Rh[3], Rl[3]);   // row g+8, nt=2cc+1
            const int n0 = 2 * cc, n1 = 2 * cc + 1;
            c1p0 += acc[n0][0] * e00.x + acc[n0][1] * e00.y + acc[n1][0] * e10.x + acc[n1][1] * e10.y;
            c1p1 += acc[n0][2] * e01.x + acc[n0][3] * e01.y + acc[n1][2] * e11.x + acc[n1][3] * e11.y;
            c2p0 += acc[n0][0] * acc[n0][0] + acc[n0][1] * acc[n0][1] + acc[n1][0] * acc[n1][0] + acc[n1][1] * acc[n1][1];
            c2p1 += acc[n0][2] * acc[n0][2] + acc[n0][3] * acc[n0][3] + acc[n1][2] * acc[n1][2] + acc[n1][3] * acc[n1][3];
        }
        c1p0 += __shfl_xor_sync(0xffffffffu, c1p0, 1);
        c1p1 += __shfl_xor_sync(0xffffffffu, c1p1, 1);
        c2p0 += __shfl_xor_sync(0xffffffffu, c2p0, 1);
        c2p1 += __shfl_xor_sync(0xffffffffu, c2p1, 1);
        c1p0 += __shfl_xor_sync(0xffffffffu, c1p0, 2);
        c1p1 += __shfl_xor_sync(0xffffffffu, c1p1, 2);
        c2p0 += __shfl_xor_sync(0xffffffffu, c2p0, 2);
        c2p1 += __shfl_xor_sync(0xffffffffu, c2p1, 2);
        if (tg == 0) {
            sc1[m0 + g] = c1p0; sc1[m0 + g + 8] = c1p1;
            sc2[m0 + g] = c2p0; sc2[m0 + g + 8] = c2p1;
        }
    }
    __syncthreads();

    // ===================== two GAT layers =====================
    for (int layer = 0; layer < 2; layer++) {
        // ---- hs = W1 @ src + b via MMA ----
        {
            float acc[4] = {0.f, 0.f, 0.f, 0.f};
#pragma unroll
            for (int ks = 0; ks < 4; ks++) {
                const int k0 = ks * 16;
                float2 v0 = *(const float2*)&ssrc[k0 + 2 * tg];
                float2 v1 = *(const float2*)&ssrc[k0 + 2 * tg + 8];
                unsigned h0, lo0, h1, lo1;
                split2(v0, h0, lo0);
                split2(v1, h1, lo1);
                unsigned B0 = (g == 0) ? h0 : (g == 1) ? lo0 : 0u;
                unsigned B1 = (g == 0) ? h1 : (g == 1) ? lo1 : 0u;
                uint4 Ah = g_AW1hi[(w * 4 + ks) * 32 + l];
                uint4 Al = g_AW1lo[(w * 4 + ks) * 32 + l];
                MMA(acc, ((unsigned*)&Ah), B0, B1);
                MMA(acc, ((unsigned*)&Al), B0, B1);
            }
            if (tg == 0) {
                shs[m0 + g] = acc[0] + acc[1] + sb[m0 + g];
                shs[m0 + g + 8] = acc[2] + acc[3] + sb[m0 + g + 8];
            }
        }
        __syncthreads();
        // ---- g = W2^T @ hs via MMA ----
        {
            float acc[4] = {0.f, 0.f, 0.f, 0.f};
#pragma unroll
            for (int ks = 0; ks < 4; ks++) {
                const int k0 = ks * 16;
                float2 v0 = *(const float2*)&shs[k0 + 2 * tg];
                float2 v1 = *(const float2*)&shs[k0 + 2 * tg + 8];
                unsigned h0, lo0, h1, lo1;
                split2(v0, h0, lo0);
                split2(v1, h1, lo1);
                unsigned B0 = (g == 0) ? h0 : (g == 1) ? lo0 : 0u;
                unsigned B1 = (g == 0) ? h1 : (g == 1) ? lo1 : 0u;
                uint4 Ah = g_AW2hi[(w * 4 + ks) * 32 + l];
                uint4 Al = g_AW2lo[(w * 4 + ks) * 32 + l];
                MMA(acc, ((unsigned*)&Ah), B0, B1);
                MMA(acc, ((unsigned*)&Al), B0, B1);
            }
            if (tg == 0) {
                sg[m0 + g] = acc[0] + acc[1];
                sg[m0 + g + 8] = acc[2] + acc[3];
            }
        }
        __syncthreads();
        // ---- dots via MMA with ldmatrix A fragments from smem ----
        {
            const float* vecp = (g & 2) ? sg : shs;
            const unsigned isLo = g & 1;
            float accR[4] = {0.f, 0.f, 0.f, 0.f};
            float accD[4] = {0.f, 0.f, 0.f, 0.f};
#pragma unroll
            for (int ks = 0; ks < 4; ks++) {
                const int k0 = ks * 16;
                float2 v0 = *(const float2*)&vecp[k0 + 2 * tg];
                float2 v1 = *(const float2*)&vecp[k0 + 2 * tg + 8];
                unsigned h0, lo0, h1, lo1;
                split2(v0, h0, lo0);
                split2(v1, h1, lo1);
                unsigned B0 = isLo ? lo0 : h0;
                unsigned B1 = isLo ? lo1 : h1;
                if (g >= 4) { B0 = 0u; B1 = 0u; }
                unsigned F[4];
                ldmat4(F, aRhi + lmrow + ks * 32);
                MMA(accR, F, B0, B1);
                ldmat4(F, aRlo + lmrow + ks * 32);
                MMA(accR, F, B0, B1);
                ldmat4(F, aDhi + lmrow + ks * 32);
                MMA(accD, F, B0, B1);
                ldmat4(F, aDlo + lmrow + ks * 32);
                MMA(accD, F, B0, B1);
            }
            if (tg == 0) { sdr[m0 + g] = accR[0] + accR[1]; sdr[m0 + g + 8] = accR[2] + accR[3]; }
            if (tg == 1) { sdh[m0 + g] = accD[0] + accD[1]; sdh[m0 + g + 8] = accD[2] + accD[3]; }
        }
        __syncthreads();
        // ---- logits + masked softmax (warp 0; s2 inline) ----
        if (t < 32) {
            float v = shs[t] * shs[t] + shs[t + 32] * shs[t + 32];
#pragma unroll
            for (int s = 16; s; s >>= 1) v += __shfl_xor_sync(0xffffffffu, v, s);
            const float s2 = v;
            float e[2];
#pragma unroll
            for (int h = 0; h < 2; h++) {
                int k = t + 32 * h;
                float num = sc1[k] + sdr[k];
                float hn2 = s2 + 2.0f * sdh[k] + sc2[k];
                float hn = sqrtf(fmaxf(hn2, 0.0f));
                float rn = sqrtf(sr2[k]);
                float den = fmaxf(hn, 1e-8f) * fmaxf(rn, 1e-8f);
                float ee = num / den;
                ee = (ee < 0.0f) ? 0.2f * ee : ee;
                e[h] = (smask[k] > 0) ? ee : -9e15f;
            }
            float m = fmaxf(e[0], e[1]);
#pragma unroll
            for (int s = 16; s; s >>= 1) m = fmaxf(m, __shfl_xor_sync(0xffffffffu, m, s));
            float x0 = __expf(e[0] - m), x1 = __expf(e[1] - m);
            float sum = x0 + x1;
#pragma unroll
            for (int s = 16; s; s >>= 1) sum += __shfl_xor_sync(0xffffffffu, sum, s);
            float inv = 1.0f / sum;
            satt[t] = x0 * inv; satt[t + 32] = x1 * inv;
        }
        __syncthreads();
        // ---- agg: lane covers col pair (2l, 2l+1), rows 16w..16w+15 from global ----
        {
            float a0 = 0.f, a1 = 0.f;
#pragma unroll
            for (int j = 0; j < 16; j++) {
                const int k = 16 * w + j;
                const float av = satt[k];
                float2 dd = *(const float2*)(gdst + k * 64 + 2 * l);
                a0 = fmaf(av, dd.x, a0);
                a1 = fmaf(av, dd.y, a1);
            }
            *(float2*)&sagg[w * 64 + 2 * l] = make_float2(a0, a1);
        }
        __syncthreads();
        if (t < D) {
            float o = (sagg[t] + sagg[64 + t]) + (sagg[128 + t] + sagg[192 + t]) + ssrc[t];
            if (layer == 0) ssrc[t] = o;
            else out[(size_t)n * D + t] = o;
        }
        __syncthreads();
    }
}

extern "C" void kernel_launch(void* const* d_in, const int* in_sizes, int n_in,
                              void* d_out, int out_size) {
    const float* src  = (const float*)d_in[0];
    const float* dst  = (const float*)d_in[1];
    const float* rel  = (const float*)d_in[2];
    const float* fcw  = (const float*)d_in[3];
    const float* fcb  = (const float*)d_in[4];
    const int*   mask = (const int*)d_in[5];
    (void)n_in;

    int N = in_sizes[0] / D;   // 50000
    float* outp = (float*)d_out;
    (void)out_size;

    prep_kernel<<<8, 256>>>(fcw);
    kgat_kernel<<<N, 128>>>(src, dst, rel, fcb, mask, outp);
}